// round 2
// baseline (speedup 1.0000x reference)
#include <cuda_runtime.h>
#include <cuda_bf16.h>
#include <cstdint>

// ---------------------------------------------------------------------------
// VQ-VAE vector quantizer, B200 (sm_100a) — bit-exact emulation of the JAX/XLA
// CPU reference numerics:
//   t_k   : dot(z_row, code_k) as single-accumulator fused-FMA chain, d=0..63
//   a_sq  : sequential  acc = fl(acc + fl(x*x)), d ascending
//   b_sq  : same, per code
//   dist  : fl( fl(a_sq - 2*t) + b_sq )      (x2 exact)
//   argmin: strict-< ascending k  (first-min, jnp tie rule)
//   z_q_st: fl( z_e + fl(z_q - z_e) )
// Speed: two codes packed per fma.rn.f32x2 lane (each lane = independent
// sequential chain -> numerics preserved, 2x FFMA rate).
// ---------------------------------------------------------------------------

#define KCODES 512
#define DIM     64
#define NROWS  (512 * 512)
#define NPAIR  (KCODES / 2)          // 256 code pairs

#define OFF_ZQ   0
#define OFF_IDX  (NROWS * DIM)                  // 16777216
#define OFF_MIND (OFF_IDX + NROWS)              // 17039360
#define OFF_CB   (OFF_MIND + NROWS)             // 17301504
#define OFF_CS   (OFF_CB + KCODES * DIM)        // 17334272
#define OFF_ES   (OFF_CS + KCODES)              // 17334784

#define SMEM_BYTES (NPAIR * DIM * 8 + KCODES * 4)   // 131072 + 2048 = 133120

__device__ __align__(16) float g_cluster[KCODES];
__device__ __align__(16) float g_embsum[KCODES * DIM];

// ---- packed fp32x2 helpers -------------------------------------------------
__device__ __forceinline__ unsigned long long pk2(float x, float y) {
    unsigned long long r;
    asm("mov.b64 %0, {%1, %2};" : "=l"(r) : "f"(x), "f"(y));
    return r;
}
__device__ __forceinline__ void upk2(unsigned long long v, float& x, float& y) {
    asm("mov.b64 {%0, %1}, %2;" : "=f"(x), "=f"(y) : "l"(v));
}
__device__ __forceinline__ void ffma2(unsigned long long& d,
                                      unsigned long long a, unsigned long long b) {
    asm("fma.rn.f32x2 %0, %1, %2, %0;" : "+l"(d) : "l"(a), "l"(b));
}
__device__ __forceinline__ void lds_v2b64(unsigned long long& a, unsigned long long& b,
                                          unsigned int addr) {
    asm("ld.shared.v2.b64 {%0, %1}, [%2];" : "=l"(a), "=l"(b) : "r"(addr));
}
__device__ __forceinline__ void red_add_v4(float* p, float a, float b, float c, float d) {
    asm volatile("red.global.add.v4.f32 [%0], {%1, %2, %3, %4};"
                 :: "l"(p), "f"(a), "f"(b), "f"(c), "f"(d) : "memory");
}

// ---- zero scratch ----------------------------------------------------------
__global__ void vq_zero() {
    int i = blockIdx.x * 256 + threadIdx.x;       // 128 * 256 = 32768 = K*D
    if (i < KCODES) g_cluster[i] = 0.0f;
    g_embsum[i] = 0.0f;
}

// ---- main ------------------------------------------------------------------
extern __shared__ float smem_raw[];

__global__ __launch_bounds__(256, 1) void vq_main(
    const float* __restrict__ z_e,
    const float* __restrict__ cbg,
    float* __restrict__ out)
{
    float2* scb2 = (float2*)smem_raw;                      // [NPAIR][DIM] interleaved pairs
    float*  sbsq = (float*)(smem_raw + NPAIR * DIM * 2);   // [KCODES]
    const int tid = threadIdx.x;

    // Stage codebook as interleaved code-pairs: scb2[p*64+d] = (cb[2p][d], cb[2p+1][d])
    for (int e = tid; e < NPAIR * DIM; e += 256) {
        int p = e >> 6, d = e & 63;
        float v0 = __ldg(&cbg[(2 * p)     * DIM + d]);
        float v1 = __ldg(&cbg[(2 * p + 1) * DIM + d]);
        scb2[e] = make_float2(v0, v1);
    }
    // b_sq per code: sequential  acc = fl(acc + fl(b*b)), d ascending
    {
        int k0 = tid, k1 = tid + 256;
        float s0 = 0.0f, s1 = 0.0f;
        for (int d = 0; d < DIM; d++) {
            float b0 = __ldg(&cbg[k0 * DIM + d]);
            float b1 = __ldg(&cbg[k1 * DIM + d]);
            s0 = __fadd_rn(s0, __fmul_rn(b0, b0));
            s1 = __fadd_rn(s1, __fmul_rn(b1, b1));
        }
        sbsq[k0] = s0; sbsq[k1] = s1;
    }
    __syncthreads();

    // One row per thread
    const int r = blockIdx.x * 256 + tid;

    // Load row; a_sq sequential (mul then add, separate roundings); pack dup lanes
    unsigned long long za2[DIM];
    float A = 0.0f;
    {
        const float4* p = (const float4*)(z_e + (size_t)r * DIM);
        #pragma unroll
        for (int i = 0; i < DIM / 4; i++) {
            float4 v = p[i];
            A = __fadd_rn(A, __fmul_rn(v.x, v.x));
            A = __fadd_rn(A, __fmul_rn(v.y, v.y));
            A = __fadd_rn(A, __fmul_rn(v.z, v.z));
            A = __fadd_rn(A, __fmul_rn(v.w, v.w));
            za2[4 * i]     = pk2(v.x, v.x);
            za2[4 * i + 1] = pk2(v.y, v.y);
            za2[4 * i + 2] = pk2(v.z, v.z);
            za2[4 * i + 3] = pk2(v.w, v.w);
        }
    }

    const unsigned int cbaddr = (unsigned int)__cvta_generic_to_shared(scb2);

    float best = 3.402823466e38f;
    int   bi   = 0;

    // 64 groups of 4 code-pairs (8 codes); each lane-half is an independent
    // strictly d-ascending fused-FMA chain (matches Eigen/cublas order).
    for (int kg = 0; kg < NPAIR / 4; kg++) {
        unsigned long long acc0 = 0ull, acc1 = 0ull, acc2 = 0ull, acc3 = 0ull;
        const unsigned int a0 = cbaddr + (unsigned int)(kg * 4 + 0) * (DIM * 8);
        const unsigned int a1 = a0 + DIM * 8;
        const unsigned int a2 = a1 + DIM * 8;
        const unsigned int a3 = a2 + DIM * 8;
        #pragma unroll
        for (int d2 = 0; d2 < DIM / 2; d2++) {
            unsigned long long p0a, p0b, p1a, p1b, p2a, p2b, p3a, p3b;
            lds_v2b64(p0a, p0b, a0 + d2 * 16);
            lds_v2b64(p1a, p1b, a1 + d2 * 16);
            lds_v2b64(p2a, p2b, a2 + d2 * 16);
            lds_v2b64(p3a, p3b, a3 + d2 * 16);
            ffma2(acc0, za2[2 * d2], p0a);
            ffma2(acc1, za2[2 * d2], p1a);
            ffma2(acc2, za2[2 * d2], p2a);
            ffma2(acc3, za2[2 * d2], p3a);
            ffma2(acc0, za2[2 * d2 + 1], p0b);
            ffma2(acc1, za2[2 * d2 + 1], p1b);
            ffma2(acc2, za2[2 * d2 + 1], p2b);
            ffma2(acc3, za2[2 * d2 + 1], p3b);
        }
        // dist = fl( fl(A - 2t) + b_sq ), compared in ascending-k order
        #pragma unroll
        for (int j = 0; j < 4; j++) {
            unsigned long long acc = (j == 0) ? acc0 : (j == 1) ? acc1 : (j == 2) ? acc2 : acc3;
            float tlo, thi;
            upk2(acc, tlo, thi);
            const int p = kg * 4 + j;
            float dlo = __fadd_rn(__fsub_rn(A, __fmul_rn(2.0f, tlo)), sbsq[2 * p]);
            float dhi = __fadd_rn(__fsub_rn(A, __fmul_rn(2.0f, thi)), sbsq[2 * p + 1]);
            if (dlo < best) { best = dlo; bi = 2 * p; }
            if (dhi < best) { best = dhi; bi = 2 * p + 1; }
        }
    }

    // ---- epilogue ----
    out[OFF_IDX + r]  = (float)bi;
    out[OFF_MIND + r] = best;

    // z_q gather (original codebook, via L2) + straight-through emulation
    {
        const float4* src = (const float4*)(cbg + (size_t)bi * DIM);
        float4* dst = (float4*)(out + (size_t)r * DIM);
        #pragma unroll
        for (int i = 0; i < DIM / 4; i++) {
            float4 q = __ldg(&src[i]);
            float ax, ay, az, aw, t;
            upk2(za2[4 * i],     ax, t);
            upk2(za2[4 * i + 1], ay, t);
            upk2(za2[4 * i + 2], az, t);
            upk2(za2[4 * i + 3], aw, t);
            float4 o;
            o.x = __fadd_rn(ax, __fsub_rn(q.x, ax));
            o.y = __fadd_rn(ay, __fsub_rn(q.y, ay));
            o.z = __fadd_rn(az, __fsub_rn(q.z, az));
            o.w = __fadd_rn(aw, __fsub_rn(q.w, aw));
            dst[i] = o;
        }
    }

    // EMA batch statistics scatter
    atomicAdd(&g_cluster[bi], 1.0f);
    {
        float* es = &g_embsum[bi * DIM];
        #pragma unroll
        for (int i = 0; i < DIM / 4; i++) {
            float ax, ay, az, aw, t;
            upk2(za2[4 * i],     ax, t);
            upk2(za2[4 * i + 1], ay, t);
            upk2(za2[4 * i + 2], az, t);
            upk2(za2[4 * i + 3], aw, t);
            red_add_v4(es + 4 * i, ax, ay, az, aw);
        }
    }
}

// ---- finalize: EMA update + new codebook (strict fp32 roundings) -----------
__global__ void vq_finalize(const float* __restrict__ ema_cs,
                            const float* __restrict__ ema_es,
                            float* __restrict__ out)
{
    int i = blockIdx.x * 256 + threadIdx.x;      // 128 * 256 = 32768 = K*D
    int k = i >> 6;
    float ncs = __fadd_rn(__fmul_rn(0.99f, ema_cs[k]), __fmul_rn(0.01f, g_cluster[k]));
    float nes = __fadd_rn(__fmul_rn(0.99f, ema_es[i]), __fmul_rn(0.01f, g_embsum[i]));
    out[OFF_ES + i] = nes;
    out[OFF_CB + i] = __fdiv_rn(nes, __fadd_rn(ncs, 1e-5f));
    if ((i & 63) == 0) out[OFF_CS + k] = ncs;
}

// ---------------------------------------------------------------------------
extern "C" void kernel_launch(void* const* d_in, const int* in_sizes, int n_in,
                              void* d_out, int out_size)
{
    (void)in_sizes; (void)n_in; (void)out_size;
    const float* z_e    = (const float*)d_in[0];
    const float* cb     = (const float*)d_in[1];
    const float* ema_cs = (const float*)d_in[2];
    const float* ema_es = (const float*)d_in[3];
    float* out = (float*)d_out;

    cudaFuncSetAttribute(vq_main, cudaFuncAttributeMaxDynamicSharedMemorySize, SMEM_BYTES);

    vq_zero<<<128, 256>>>();
    vq_main<<<NROWS / 256, 256, SMEM_BYTES>>>(z_e, cb, out);
    vq_finalize<<<128, 256>>>(ema_cs, ema_es, out);
}